// round 6
// baseline (speedup 1.0000x reference)
#include <cuda_runtime.h>
#include <cuda_bf16.h>
#include <cstdint>

// h (projected features) stored naturally [b][j][f] as bf16 hi/lo pair.
__device__ __align__(16) __nv_bfloat16 g_h_hi[4 * 2048 * 128];
__device__ __align__(16) __nv_bfloat16 g_h_lo[4 * 2048 * 128];
__device__ float g_s[4 * 2048];

static __device__ __forceinline__ uint32_t smem_u32(const void* p) {
    uint32_t a;
    asm("{ .reg .u64 t; cvta.to.shared.u64 t, %1; cvt.u32.u64 %0, t; }" : "=r"(a) : "l"(p));
    return a;
}
static __device__ __forceinline__ void mbar_init(uint32_t a, uint32_t cnt) {
    asm volatile("mbarrier.init.shared.b64 [%0], %1;" :: "r"(a), "r"(cnt) : "memory");
}
static __device__ __forceinline__ void mbar_arrive(uint32_t a) {
    asm volatile("mbarrier.arrive.shared.b64 _, [%0];" :: "r"(a) : "memory");
}
static __device__ __forceinline__ void mbar_cp_arrive(uint32_t a) {
    asm volatile("cp.async.mbarrier.arrive.shared.b64 [%0];" :: "r"(a) : "memory");
}
static __device__ __forceinline__ void mbar_wait(uint32_t a, uint32_t par) {
    asm volatile(
        "{\n .reg .pred P;\n"
        "WL%=: mbarrier.try_wait.parity.shared.b64 P, [%0], %1;\n"
        " @P bra WD%=;\n bra WL%=;\n WD%=:\n}"
        :: "r"(a), "r"(par) : "memory");
}
static __device__ __forceinline__ void cp16(uint32_t dst, const void* src) {
    asm volatile("cp.async.cg.shared.global [%0], [%1], 16;" :: "r"(dst), "l"(src) : "memory");
}
static __device__ __forceinline__ void ldsm4(uint32_t* r, uint32_t a) {
    asm volatile("ldmatrix.sync.aligned.m8n8.x4.shared.b16 {%0,%1,%2,%3}, [%4];"
                 : "=r"(r[0]), "=r"(r[1]), "=r"(r[2]), "=r"(r[3]) : "r"(a));
}
static __device__ __forceinline__ void ldsm4t(uint32_t* r, uint32_t a) {
    asm volatile("ldmatrix.sync.aligned.m8n8.x4.trans.shared.b16 {%0,%1,%2,%3}, [%4];"
                 : "=r"(r[0]), "=r"(r[1]), "=r"(r[2]), "=r"(r[3]) : "r"(a));
}
static __device__ __forceinline__ void mma16816(float* c, const uint32_t* a,
                                                uint32_t b0, uint32_t b1) {
    asm volatile(
        "mma.sync.aligned.m16n8k16.row.col.f32.bf16.bf16.f32 "
        "{%0,%1,%2,%3}, {%4,%5,%6,%7}, {%8,%9}, {%0,%1,%2,%3};"
        : "+f"(c[0]), "+f"(c[1]), "+f"(c[2]), "+f"(c[3])
        : "r"(a[0]), "r"(a[1]), "r"(a[2]), "r"(a[3]), "r"(b0), "r"(b1));
}

// ---------------- K1: h = x@W (fp32), s = h@a_w + a_b, h -> bf16 hi/lo -----
__global__ void __launch_bounds__(256) k_prep(const float* __restrict__ x,
                                              const float* __restrict__ W,
                                              const float* __restrict__ aw,
                                              const float* __restrict__ ab) {
    extern __shared__ float sm1[];
    float* xs = sm1;             // [64][132]
    float* ws = sm1 + 64 * 132;  // [128][128]
    const int tid = threadIdx.x;
    const int b = blockIdx.x >> 5;
    const int i0 = (blockIdx.x & 31) * 64;

    const float* xb = x + ((size_t)b * 2048 + i0) * 128;
#pragma unroll
    for (int k = 0; k < 32; k++) {
        int idx = tid + 256 * k;
        xs[(idx >> 7) * 132 + (idx & 127)] = xb[idx];
    }
#pragma unroll 8
    for (int k = 0; k < 64; k++) {
        int idx = tid + 256 * k;
        ws[idx] = W[idx];
    }
    __syncthreads();

    const int fg = tid & 15, rg = tid >> 4;
    const int f0 = fg * 8, r0 = rg * 4;
    float acc[4][8];
#pragma unroll
    for (int i = 0; i < 4; i++)
#pragma unroll
        for (int j = 0; j < 8; j++) acc[i][j] = 0.f;

#pragma unroll 4
    for (int k = 0; k < 128; k++) {
        float4 w0 = *(const float4*)&ws[k * 128 + f0];
        float4 w1 = *(const float4*)&ws[k * 128 + f0 + 4];
#pragma unroll
        for (int i = 0; i < 4; i++) {
            float a = xs[(r0 + i) * 132 + k];
            acc[i][0] += a * w0.x; acc[i][1] += a * w0.y;
            acc[i][2] += a * w0.z; acc[i][3] += a * w0.w;
            acc[i][4] += a * w1.x; acc[i][5] += a * w1.y;
            acc[i][6] += a * w1.z; acc[i][7] += a * w1.w;
        }
    }

    float awv[8];
#pragma unroll
    for (int j = 0; j < 8; j++) awv[j] = aw[f0 + j];
#pragma unroll
    for (int i = 0; i < 4; i++) {
        float s = 0.f;
#pragma unroll
        for (int j = 0; j < 8; j++) s += acc[i][j] * awv[j];
#pragma unroll
        for (int off = 8; off >= 1; off >>= 1) s += __shfl_xor_sync(0xffffffffu, s, off);
        if (fg == 0) g_s[b * 2048 + i0 + r0 + i] = s + ab[0];
    }

    // h -> bf16 hi/lo, natural layout [b][row][f], 16B stores
#pragma unroll
    for (int i = 0; i < 4; i++) {
        size_t base = ((size_t)b * 2048 + i0 + r0 + i) * 128 + f0;
        __nv_bfloat162 h2[4], l2[4];
#pragma unroll
        for (int q = 0; q < 4; q++) {
            float v0 = acc[i][2 * q], v1 = acc[i][2 * q + 1];
            __nv_bfloat16 h0 = __float2bfloat16_rn(v0);
            __nv_bfloat16 h1 = __float2bfloat16_rn(v1);
            h2[q] = __halves2bfloat162(h0, h1);
            l2[q] = __halves2bfloat162(__float2bfloat16_rn(v0 - __bfloat162float(h0)),
                                       __float2bfloat16_rn(v1 - __bfloat162float(h1)));
        }
        *(uint4*)(g_h_hi + base) = *(uint4*)h2;
        *(uint4*)(g_h_lo + base) = *(uint4*)l2;
    }
}

// ---------------- K2: warp-specialized softmax + P@h via HMMA --------------
// 512 threads: warps 0-7 = MMA (2 per SMSP), warps 8-15 = producers.
// 4-stage circular pipeline. Per stage:
//   Phi[64][72] Plo[64][72] (pitch 144B), Hhi[64][136] Hlo[64][136] (272B)
static constexpr int NSTAGE  = 4;
static constexpr int P_PITCH = 144;
static constexpr int H_PITCH = 272;
static constexpr int OFF_PLO = 64 * P_PITCH;            // 9216
static constexpr int OFF_HHI = 2 * 64 * P_PITCH;        // 18432
static constexpr int OFF_HLO = OFF_HHI + 64 * H_PITCH;  // 35840
static constexpr int SBUF    = OFF_HLO + 64 * H_PITCH;  // 53248
static constexpr int OFF_SS   = NSTAGE * SBUF;          // 212992 (2048 f)
static constexpr int OFF_BIAS = OFF_SS + 8192;          // 221184 (128 f)
static constexpr int OFF_LS   = OFF_BIAS + 512;         // 221696 (64 f)
static constexpr int OFF_MB   = OFF_LS + 256;           // 221952 (8 mbarriers)
static constexpr int SM2_SIZE = OFF_MB + 64;            // 222016

__global__ void __launch_bounds__(512) k_attn(const float* __restrict__ A,
                                              const float* __restrict__ bias,
                                              float* __restrict__ out) {
    extern __shared__ char sm[];
    const uint32_t sb = smem_u32(sm);
    const int tid = threadIdx.x, wid = tid >> 5, lane = tid & 31;
    const int b = blockIdx.x >> 5;
    const int i0 = (blockIdx.x & 31) << 6;

    float* ss = (float*)(sm + OFF_SS);
    {   // preload s for whole batch + bias
        const float4* sg = (const float4*)(g_s + b * 2048);
        float4* d = (float4*)ss;
        d[tid] = sg[tid];
        if (tid < 128) ((float*)(sm + OFF_BIAS))[tid] = bias[tid];
    }
    if (tid == 0) {
#pragma unroll
        for (int s = 0; s < NSTAGE; s++) {
            mbar_init(sb + OFF_MB + 8 * s, 256);                // full[s]
            mbar_init(sb + OFF_MB + 8 * (NSTAGE + s), 256);     // empty[s]
        }
    }
    __syncthreads();

    if (wid >= 8) {
        // ---------------- producer: P = exp(leaky(s_i+s_j)+A), H copies ----
        const int p = tid - 256;                         // 0..255
        const int rbase = p >> 4, cbase = (p & 15) * 4;  // 4 rows x 4 cols per thread
        const int fc = p & 15, jrb = p >> 4;
        const float* Abase = A + ((size_t)b * 2048 + i0) * 2048;
        const __nv_bfloat16* Hhig = g_h_hi + (size_t)b * 2048 * 128;
        const __nv_bfloat16* Hlog = g_h_lo + (size_t)b * 2048 * 128;

        float s_i[4], lsum[4];
#pragma unroll
        for (int it = 0; it < 4; it++) {
            s_i[it] = ss[i0 + rbase + 16 * it];
            lsum[it] = 0.f;
        }
        int phe[NSTAGE] = {1, 1, 1, 1};

#pragma unroll 1
        for (int t = 0; t < 32; t++) {
            const int j0 = t * 64, st = t & (NSTAGE - 1);
            const uint32_t bb = sb + st * SBUF;
            char* bp = sm + st * SBUF;

            // global A loads first (registers only; buffer may be busy)
            float4 av[4];
#pragma unroll
            for (int it = 0; it < 4; it++)
                av[it] = *(const float4*)(Abase + (size_t)(rbase + 16 * it) * 2048 + j0 + cbase);

            mbar_wait(sb + OFF_MB + 8 * (NSTAGE + st), phe[st]);
            phe[st] ^= 1;

            // h tiles via cp.async: 64 rows x 16 col-chunks (16B) per hi/lo
#pragma unroll
            for (int c = 0; c < 4; c++) {
                const int jr = jrb + 16 * c;
                const size_t gsrc = (size_t)(j0 + jr) * 128 + fc * 8;
                cp16(bb + OFF_HHI + jr * H_PITCH + fc * 16, Hhig + gsrc);
                cp16(bb + OFF_HLO + jr * H_PITCH + fc * 16, Hlog + gsrc);
            }
            // async completion arrives on full[st]; no blocking wait
            mbar_cp_arrive(sb + OFF_MB + 8 * st);

            const float4 sv = *(const float4*)(ss + j0 + cbase);
#pragma unroll
            for (int it = 0; it < 4; it++) {
                const float si = s_i[it];
                float e0 = si + sv.x, e1 = si + sv.y, e2 = si + sv.z, e3 = si + sv.w;
                e0 = fmaxf(e0, 0.f) + 0.2f * fminf(e0, 0.f);
                e1 = fmaxf(e1, 0.f) + 0.2f * fminf(e1, 0.f);
                e2 = fmaxf(e2, 0.f) + 0.2f * fminf(e2, 0.f);
                e3 = fmaxf(e3, 0.f) + 0.2f * fminf(e3, 0.f);
                float p0 = __expf(e0 + av[it].x), p1 = __expf(e1 + av[it].y);
                float p2 = __expf(e2 + av[it].z), p3 = __expf(e3 + av[it].w);
                lsum[it] += (p0 + p1) + (p2 + p3);
                __nv_bfloat162 hA = __float22bfloat162_rn(make_float2(p0, p1));
                __nv_bfloat162 hB = __float22bfloat162_rn(make_float2(p2, p3));
                float2 fA = __bfloat1622float2(hA), fB = __bfloat1622float2(hB);
                __nv_bfloat162 lA = __float22bfloat162_rn(make_float2(p0 - fA.x, p1 - fA.y));
                __nv_bfloat162 lB = __float22bfloat162_rn(make_float2(p2 - fB.x, p3 - fB.y));
                char* dst = bp + (rbase + 16 * it) * P_PITCH + cbase * 2;
                *(uint2*)dst = make_uint2(*(uint32_t*)&hA, *(uint32_t*)&hB);
                *(uint2*)(dst + OFF_PLO) = make_uint2(*(uint32_t*)&lA, *(uint32_t*)&lB);
            }
            mbar_arrive(sb + OFF_MB + 8 * st);
        }

        // per-row sums -> smem (16 lanes share a row)
        float* ls = (float*)(sm + OFF_LS);
#pragma unroll
        for (int it = 0; it < 4; it++) {
            float v = lsum[it];
            v += __shfl_xor_sync(0xffffffffu, v, 1);
            v += __shfl_xor_sync(0xffffffffu, v, 2);
            v += __shfl_xor_sync(0xffffffffu, v, 4);
            v += __shfl_xor_sync(0xffffffffu, v, 8);
            if ((p & 15) == 0) ls[rbase + 16 * it] = v;
        }
    } else {
        // ---------------- consumer: 16 rows x 64 cols per warp -------------
        const int r0 = (wid & 3) * 16;       // SMSP = wid&3; 2 warps/SMSP
        const int c0 = (wid >> 2) * 64;
        float acc[8][4];
#pragma unroll
        for (int nb = 0; nb < 8; nb++)
#pragma unroll
            for (int q = 0; q < 4; q++) acc[nb][q] = 0.f;

        const uint32_t arow = (uint32_t)((r0 + (lane & 15)) * P_PITCH + ((lane >> 4) << 4));
        const uint32_t brow = (uint32_t)((lane & 15) * H_PITCH + ((lane >> 4) << 4) + c0 * 2);
        int phf[NSTAGE] = {0, 0, 0, 0};

#pragma unroll 1
        for (int t = 0; t < 32; t++) {
            const int st = t & (NSTAGE - 1);
            const uint32_t bb = sb + st * SBUF;
            mbar_wait(sb + OFF_MB + 8 * st, phf[st]);
            phf[st] ^= 1;

#pragma unroll
            for (int kk = 0; kk < 4; kk++) {
                uint32_t aph[4], apl[4];
                ldsm4(aph, bb + arow + kk * 32);
                ldsm4(apl, bb + OFF_PLO + arow + kk * 32);
                const uint32_t hb = bb + OFF_HHI + brow + kk * 16 * H_PITCH;
                uint32_t bh[4][4], bl[4][4];
#pragma unroll
                for (int n0 = 0; n0 < 4; n0++) {
                    ldsm4t(bh[n0], hb + n0 * 32);
                    ldsm4t(bl[n0], hb + (OFF_HLO - OFF_HHI) + n0 * 32);
                }
#pragma unroll
                for (int n0 = 0; n0 < 4; n0++) {
                    mma16816(acc[2 * n0],     aph, bh[n0][0], bh[n0][1]);
                    mma16816(acc[2 * n0 + 1], aph, bh[n0][2], bh[n0][3]);
                }
#pragma unroll
                for (int n0 = 0; n0 < 4; n0++) {
                    mma16816(acc[2 * n0],     apl, bh[n0][0], bh[n0][1]);
                    mma16816(acc[2 * n0 + 1], apl, bh[n0][2], bh[n0][3]);
                }
#pragma unroll
                for (int n0 = 0; n0 < 4; n0++) {
                    mma16816(acc[2 * n0],     aph, bl[n0][0], bl[n0][1]);
                    mma16816(acc[2 * n0 + 1], aph, bl[n0][2], bl[n0][3]);
                }
            }
            mbar_arrive(sb + OFF_MB + 8 * (NSTAGE + st));
        }

        __syncthreads();  // producers publish ls

        const float* ls = (const float*)(sm + OFF_LS);
        const float* bs = (const float*)(sm + OFF_BIAS);
        const int row_lo = r0 + (lane >> 2);
        const float linv0 = 1.0f / ls[row_lo];
        const float linv1 = 1.0f / ls[row_lo + 8];
        float* orow0 = out + ((size_t)b * 2048 + i0 + row_lo) * 128;
        float* orow1 = orow0 + 8 * 128;
#pragma unroll
        for (int nb = 0; nb < 8; nb++) {
            const int col = c0 + nb * 8 + (lane & 3) * 2;
            float2 o0 = make_float2(acc[nb][0] * linv0 + bs[col],
                                    acc[nb][1] * linv0 + bs[col + 1]);
            float2 o1 = make_float2(acc[nb][2] * linv1 + bs[col],
                                    acc[nb][3] * linv1 + bs[col + 1]);
            *(float2*)(orow0 + col) = o0;
            *(float2*)(orow1 + col) = o1;
        }
        return;  // consumers done (producers hit the syncthreads below)
    }
    __syncthreads();  // producers: pair with consumers' syncthreads
}

extern "C" void kernel_launch(void* const* d_in, const int* in_sizes, int n_in,
                              void* d_out, int out_size) {
    (void)in_sizes; (void)n_in; (void)out_size;
    const float* x    = (const float*)d_in[0];
    const float* A    = (const float*)d_in[1];
    const float* W    = (const float*)d_in[2];
    const float* aw   = (const float*)d_in[3];
    const float* ab   = (const float*)d_in[4];
    const float* bias = (const float*)d_in[5];
    float* out = (float*)d_out;

    cudaFuncSetAttribute(k_prep, cudaFuncAttributeMaxDynamicSharedMemorySize, 99328);
    cudaFuncSetAttribute(k_attn, cudaFuncAttributeMaxDynamicSharedMemorySize, SM2_SIZE);

    k_prep<<<128, 256, 99328>>>(x, W, aw, ab);
    k_attn<<<128, 512, SM2_SIZE>>>(A, bias, out);
}

// round 7
// speedup vs baseline: 1.1710x; 1.1710x over previous
#include <cuda_runtime.h>
#include <cuda_fp16.h>
#include <cstdint>

// h (projected features) stored naturally [b][j][f] as fp16 hi/lo pair.
__device__ __align__(16) __half g_h_hi[4 * 2048 * 128];
__device__ __align__(16) __half g_h_lo[4 * 2048 * 128];
__device__ float g_s[4 * 2048];

static __device__ __forceinline__ uint32_t smem_u32(const void* p) {
    uint32_t a;
    asm("{ .reg .u64 t; cvta.to.shared.u64 t, %1; cvt.u32.u64 %0, t; }" : "=r"(a) : "l"(p));
    return a;
}
static __device__ __forceinline__ void mbar_init(uint32_t a, uint32_t cnt) {
    asm volatile("mbarrier.init.shared.b64 [%0], %1;" :: "r"(a), "r"(cnt) : "memory");
}
static __device__ __forceinline__ void mbar_arrive(uint32_t a) {
    asm volatile("mbarrier.arrive.shared.b64 _, [%0];" :: "r"(a) : "memory");
}
static __device__ __forceinline__ void mbar_cp_arrive(uint32_t a) {
    asm volatile("cp.async.mbarrier.arrive.shared.b64 [%0];" :: "r"(a) : "memory");
}
static __device__ __forceinline__ void mbar_wait(uint32_t a, uint32_t par) {
    asm volatile(
        "{\n .reg .pred P;\n"
        "WL%=: mbarrier.try_wait.parity.shared.b64 P, [%0], %1;\n"
        " @P bra WD%=;\n bra WL%=;\n WD%=:\n}"
        :: "r"(a), "r"(par) : "memory");
}
static __device__ __forceinline__ void cp16(uint32_t dst, const void* src) {
    asm volatile("cp.async.cg.shared.global [%0], [%1], 16;" :: "r"(dst), "l"(src) : "memory");
}
static __device__ __forceinline__ void ldsm4(uint32_t* r, uint32_t a) {
    asm volatile("ldmatrix.sync.aligned.m8n8.x4.shared.b16 {%0,%1,%2,%3}, [%4];"
                 : "=r"(r[0]), "=r"(r[1]), "=r"(r[2]), "=r"(r[3]) : "r"(a));
}
static __device__ __forceinline__ void ldsm4t(uint32_t* r, uint32_t a) {
    asm volatile("ldmatrix.sync.aligned.m8n8.x4.trans.shared.b16 {%0,%1,%2,%3}, [%4];"
                 : "=r"(r[0]), "=r"(r[1]), "=r"(r[2]), "=r"(r[3]) : "r"(a));
}
static __device__ __forceinline__ void mma16816(float* c, const uint32_t* a,
                                                uint32_t b0, uint32_t b1) {
    asm volatile(
        "mma.sync.aligned.m16n8k16.row.col.f32.f16.f16.f32 "
        "{%0,%1,%2,%3}, {%4,%5,%6,%7}, {%8,%9}, {%0,%1,%2,%3};"
        : "+f"(c[0]), "+f"(c[1]), "+f"(c[2]), "+f"(c[3])
        : "r"(a[0]), "r"(a[1]), "r"(a[2]), "r"(a[3]), "r"(b0), "r"(b1));
}
static __device__ __forceinline__ float leaky(float x) {
    return fmaxf(x, 0.f) + 0.2f * fminf(x, 0.f);
}

// ---------------- K1: h = x@W (fp32), s = h@a_w + a_b, h -> fp16 hi/lo -----
__global__ void __launch_bounds__(256) k_prep(const float* __restrict__ x,
                                              const float* __restrict__ W,
                                              const float* __restrict__ aw,
                                              const float* __restrict__ ab) {
    extern __shared__ float sm1[];
    float* xs = sm1;             // [64][132]
    float* ws = sm1 + 64 * 132;  // [128][128]
    const int tid = threadIdx.x;
    const int b = blockIdx.x >> 5;
    const int i0 = (blockIdx.x & 31) * 64;

    const float* xb = x + ((size_t)b * 2048 + i0) * 128;
#pragma unroll
    for (int k = 0; k < 32; k++) {
        int idx = tid + 256 * k;
        xs[(idx >> 7) * 132 + (idx & 127)] = xb[idx];
    }
#pragma unroll 8
    for (int k = 0; k < 64; k++) {
        int idx = tid + 256 * k;
        ws[idx] = W[idx];
    }
    __syncthreads();

    const int fg = tid & 15, rg = tid >> 4;
    const int f0 = fg * 8, r0 = rg * 4;
    float acc[4][8];
#pragma unroll
    for (int i = 0; i < 4; i++)
#pragma unroll
        for (int j = 0; j < 8; j++) acc[i][j] = 0.f;

#pragma unroll 4
    for (int k = 0; k < 128; k++) {
        float4 w0 = *(const float4*)&ws[k * 128 + f0];
        float4 w1 = *(const float4*)&ws[k * 128 + f0 + 4];
#pragma unroll
        for (int i = 0; i < 4; i++) {
            float a = xs[(r0 + i) * 132 + k];
            acc[i][0] += a * w0.x; acc[i][1] += a * w0.y;
            acc[i][2] += a * w0.z; acc[i][3] += a * w0.w;
            acc[i][4] += a * w1.x; acc[i][5] += a * w1.y;
            acc[i][6] += a * w1.z; acc[i][7] += a * w1.w;
        }
    }

    float awv[8];
#pragma unroll
    for (int j = 0; j < 8; j++) awv[j] = aw[f0 + j];
#pragma unroll
    for (int i = 0; i < 4; i++) {
        float s = 0.f;
#pragma unroll
        for (int j = 0; j < 8; j++) s += acc[i][j] * awv[j];
#pragma unroll
        for (int off = 8; off >= 1; off >>= 1) s += __shfl_xor_sync(0xffffffffu, s, off);
        if (fg == 0) g_s[b * 2048 + i0 + r0 + i] = s + ab[0];
    }

    // h -> fp16 hi/lo, natural layout [b][row][f], 16B stores
#pragma unroll
    for (int i = 0; i < 4; i++) {
        size_t base = ((size_t)b * 2048 + i0 + r0 + i) * 128 + f0;
        __half2 h2[4], l2[4];
#pragma unroll
        for (int q = 0; q < 4; q++) {
            float v0 = acc[i][2 * q], v1 = acc[i][2 * q + 1];
            __half h0 = __float2half_rn(v0);
            __half h1 = __float2half_rn(v1);
            h2[q] = __halves2half2(h0, h1);
            l2[q] = __halves2half2(__float2half_rn(v0 - __half2float(h0)),
                                   __float2half_rn(v1 - __half2float(h1)));
        }
        *(uint4*)(g_h_hi + base) = *(uint4*)h2;
        *(uint4*)(g_h_lo + base) = *(uint4*)l2;
    }
}

// ---------------- K2: warp-specialized softmax + P@h via fp16 HMMA ---------
// 512 threads: warps 0-7 = MMA (2 per SMSP), warps 8-15 = producers.
// 4-stage pipeline. Per stage: P[64][72]h (144B pitch), Hhi/Hlo[64][136]h (272B)
static constexpr int NSTAGE  = 4;
static constexpr int P_PITCH = 144;
static constexpr int H_PITCH = 272;
static constexpr int OFF_HHI = 64 * P_PITCH;            // 9216
static constexpr int OFF_HLO = OFF_HHI + 64 * H_PITCH;  // 26624
static constexpr int SBUF    = OFF_HLO + 64 * H_PITCH;  // 44032
static constexpr int OFF_SS   = NSTAGE * SBUF;          // 176128 (2048 f)
static constexpr int OFF_BIAS = OFF_SS + 8192;          // 184320 (128 f)
static constexpr int OFF_LS   = OFF_BIAS + 512;         // 184832 (64 f)
static constexpr int OFF_SMAX = OFF_LS + 256;           // 185088 (1 f + pad)
static constexpr int OFF_MB   = OFF_SMAX + 16;          // 185104 (8 mbarriers)
static constexpr int SM2_SIZE = OFF_MB + 64;            // 185168

__global__ void __launch_bounds__(512) k_attn(const float* __restrict__ A,
                                              const float* __restrict__ bias,
                                              float* __restrict__ out) {
    extern __shared__ char sm[];
    const uint32_t sb = smem_u32(sm);
    const int tid = threadIdx.x, wid = tid >> 5, lane = tid & 31;
    const int b = blockIdx.x >> 5;
    const int i0 = (blockIdx.x & 31) << 6;

    float* ss = (float*)(sm + OFF_SS);
    {   // preload s for whole batch + bias
        const float4* sg = (const float4*)(g_s + b * 2048);
        float4* d = (float4*)ss;
        d[tid] = sg[tid];
        if (tid < 128) ((float*)(sm + OFF_BIAS))[tid] = bias[tid];
    }
    if (tid == 0) {
#pragma unroll
        for (int s = 0; s < NSTAGE; s++) {
            mbar_init(sb + OFF_MB + 8 * s, 256);                // full[s]
            mbar_init(sb + OFF_MB + 8 * (NSTAGE + s), 256);     // empty[s]
        }
    }
    __syncthreads();

    // batch-wide max of s (for fp16-safe exp shift) -- all 512 threads
    {
        float mx = -1e30f;
        for (int k = tid; k < 2048; k += 512) mx = fmaxf(mx, ss[k]);
#pragma unroll
        for (int off = 16; off >= 1; off >>= 1)
            mx = fmaxf(mx, __shfl_xor_sync(0xffffffffu, mx, off));
        if (lane == 0) ((float*)(sm + OFF_LS))[wid] = mx;  // scratch reuse
    }
    __syncthreads();
    if (tid == 0) {
        float mx = -1e30f;
#pragma unroll
        for (int w = 0; w < 16; w++) mx = fmaxf(mx, ((float*)(sm + OFF_LS))[w]);
        *(float*)(sm + OFF_SMAX) = mx;
    }
    __syncthreads();
    const float smax = *(const float*)(sm + OFF_SMAX);

    if (wid >= 8) {
        // ---------------- producer: P = exp(leaky(s_i+s_j)+A-m_i), H copies
        const int p = tid - 256;                         // 0..255
        const int rbase = p >> 4, cbase = (p & 15) * 4;  // 4 rows x 4 cols per thread
        const int fc = p & 15, jrb = p >> 4;
        const float* Abase = A + ((size_t)b * 2048 + i0) * 2048;
        const __half* Hhig = g_h_hi + (size_t)b * 2048 * 128;
        const __half* Hlog = g_h_lo + (size_t)b * 2048 * 128;

        float s_i[4], m_i[4], lsum[4];
#pragma unroll
        for (int it = 0; it < 4; it++) {
            s_i[it] = ss[i0 + rbase + 16 * it];
            m_i[it] = leaky(s_i[it] + smax);
            lsum[it] = 0.f;
        }
        int phe[NSTAGE] = {1, 1, 1, 1};

#pragma unroll 1
        for (int t = 0; t < 32; t++) {
            const int j0 = t * 64, st = t & (NSTAGE - 1);
            const uint32_t bb = sb + st * SBUF;
            char* bp = sm + st * SBUF;

            // global A loads first (registers only; buffer may be busy)
            float4 av[4];
#pragma unroll
            for (int it = 0; it < 4; it++)
                av[it] = *(const float4*)(Abase + (size_t)(rbase + 16 * it) * 2048 + j0 + cbase);

            mbar_wait(sb + OFF_MB + 8 * (NSTAGE + st), phe[st]);
            phe[st] ^= 1;

            // h tiles via cp.async: 64 rows x 16 col-chunks (16B) per hi/lo
#pragma unroll
            for (int c = 0; c < 4; c++) {
                const int jr = jrb + 16 * c;
                const size_t gsrc = (size_t)(j0 + jr) * 128 + fc * 8;
                cp16(bb + OFF_HHI + jr * H_PITCH + fc * 16, Hhig + gsrc);
                cp16(bb + OFF_HLO + jr * H_PITCH + fc * 16, Hlog + gsrc);
            }
            mbar_cp_arrive(sb + OFF_MB + 8 * st);  // async completion -> full[st]

            const float4 sv = *(const float4*)(ss + j0 + cbase);
#pragma unroll
            for (int it = 0; it < 4; it++) {
                const float si = s_i[it], m = m_i[it];
                float e0 = leaky(si + sv.x) - m;
                float e1 = leaky(si + sv.y) - m;
                float e2 = leaky(si + sv.z) - m;
                float e3 = leaky(si + sv.w) - m;
                float p0 = __expf(e0 + av[it].x), p1 = __expf(e1 + av[it].y);
                float p2 = __expf(e2 + av[it].z), p3 = __expf(e3 + av[it].w);
                lsum[it] += (p0 + p1) + (p2 + p3);
                __half2 hA = __floats2half2_rn(p0, p1);
                __half2 hB = __floats2half2_rn(p2, p3);
                *(uint2*)(bp + (rbase + 16 * it) * P_PITCH + cbase * 2) =
                    make_uint2(*(uint32_t*)&hA, *(uint32_t*)&hB);
            }
            mbar_arrive(sb + OFF_MB + 8 * st);
        }

        // per-row sums -> smem (16 lanes share a row)
        float* ls = (float*)(sm + OFF_LS);
#pragma unroll
        for (int it = 0; it < 4; it++) {
            float v = lsum[it];
            v += __shfl_xor_sync(0xffffffffu, v, 1);
            v += __shfl_xor_sync(0xffffffffu, v, 2);
            v += __shfl_xor_sync(0xffffffffu, v, 4);
            v += __shfl_xor_sync(0xffffffffu, v, 8);
            if ((p & 15) == 0) ls[rbase + 16 * it] = v;
        }
    } else {
        // ---------------- consumer: 16 rows x 64 cols per warp -------------
        const int r0 = (wid & 3) * 16;       // SMSP = wid&3; 2 warps/SMSP
        const int c0 = (wid >> 2) * 64;
        float acc[8][4];
#pragma unroll
        for (int nb = 0; nb < 8; nb++)
#pragma unroll
            for (int q = 0; q < 4; q++) acc[nb][q] = 0.f;

        const uint32_t arow = (uint32_t)((r0 + (lane & 15)) * P_PITCH + ((lane >> 4) << 4));
        const uint32_t brow = (uint32_t)((lane & 15) * H_PITCH + ((lane >> 4) << 4) + c0 * 2);
        int phf[NSTAGE] = {0, 0, 0, 0};

#pragma unroll 1
        for (int t = 0; t < 32; t++) {
            const int st = t & (NSTAGE - 1);
            const uint32_t bb = sb + st * SBUF;
            mbar_wait(sb + OFF_MB + 8 * st, phf[st]);
            phf[st] ^= 1;

#pragma unroll
            for (int kk = 0; kk < 4; kk++) {
                uint32_t ap[4];
                ldsm4(ap, bb + arow + kk * 32);
                const uint32_t hb = bb + OFF_HHI + brow + kk * 16 * H_PITCH;
                uint32_t bh[4][4], bl[4][4];
#pragma unroll
                for (int n0 = 0; n0 < 4; n0++) {
                    ldsm4t(bh[n0], hb + n0 * 32);
                    ldsm4t(bl[n0], hb + (OFF_HLO - OFF_HHI) + n0 * 32);
                }
#pragma unroll
                for (int n0 = 0; n0 < 4; n0++) {
                    mma16816(acc[2 * n0],     ap, bh[n0][0], bh[n0][1]);
                    mma16816(acc[2 * n0 + 1], ap, bh[n0][2], bh[n0][3]);
                }
#pragma unroll
                for (int n0 = 0; n0 < 4; n0++) {
                    mma16816(acc[2 * n0],     ap, bl[n0][0], bl[n0][1]);
                    mma16816(acc[2 * n0 + 1], ap, bl[n0][2], bl[n0][3]);
                }
            }
            mbar_arrive(sb + OFF_MB + 8 * (NSTAGE + st));
        }

        __syncthreads();  // producers publish ls

        const float* ls = (const float*)(sm + OFF_LS);
        const float* bs = (const float*)(sm + OFF_BIAS);
        const int row_lo = r0 + (lane >> 2);
        const float linv0 = 1.0f / ls[row_lo];
        const float linv1 = 1.0f / ls[row_lo + 8];
        float* orow0 = out + ((size_t)b * 2048 + i0 + row_lo) * 128;
        float* orow1 = orow0 + 8 * 128;
#pragma unroll
        for (int nb = 0; nb < 8; nb++) {
            const int col = c0 + nb * 8 + (lane & 3) * 2;
            float2 o0 = make_float2(acc[nb][0] * linv0 + bs[col],
                                    acc[nb][1] * linv0 + bs[col + 1]);
            float2 o1 = make_float2(acc[nb][2] * linv1 + bs[col],
                                    acc[nb][3] * linv1 + bs[col + 1]);
            *(float2*)(orow0 + col) = o0;
            *(float2*)(orow1 + col) = o1;
        }
        return;  // consumers done (producers hit the syncthreads below)
    }
    __syncthreads();  // producers: pair with consumers' syncthreads
}

extern "C" void kernel_launch(void* const* d_in, const int* in_sizes, int n_in,
                              void* d_out, int out_size) {
    (void)in_sizes; (void)n_in; (void)out_size;
    const float* x    = (const float*)d_in[0];
    const float* A    = (const float*)d_in[1];
    const float* W    = (const float*)d_in[2];
    const float* aw   = (const float*)d_in[3];
    const float* ab   = (const float*)d_in[4];
    const float* bias = (const float*)d_in[5];
    float* out = (float*)d_out;

    cudaFuncSetAttribute(k_prep, cudaFuncAttributeMaxDynamicSharedMemorySize, 99328);
    cudaFuncSetAttribute(k_attn, cudaFuncAttributeMaxDynamicSharedMemorySize, SM2_SIZE);

    k_prep<<<128, 256, 99328>>>(x, W, aw, ab);
    k_attn<<<128, 512, SM2_SIZE>>>(A, bias, out);
}

// round 8
// speedup vs baseline: 1.4734x; 1.2582x over previous
#include <cuda_runtime.h>
#include <cuda_fp16.h>
#include <cstdint>

// h (projected features) stored naturally [b][j][f] as fp16.
__device__ __align__(16) __half g_h_hi[4 * 2048 * 128];
__device__ float g_s[4 * 2048];

static __device__ __forceinline__ uint32_t smem_u32(const void* p) {
    uint32_t a;
    asm("{ .reg .u64 t; cvta.to.shared.u64 t, %1; cvt.u32.u64 %0, t; }" : "=r"(a) : "l"(p));
    return a;
}
static __device__ __forceinline__ void mbar_init(uint32_t a, uint32_t cnt) {
    asm volatile("mbarrier.init.shared.b64 [%0], %1;" :: "r"(a), "r"(cnt) : "memory");
}
static __device__ __forceinline__ void mbar_arrive(uint32_t a) {
    asm volatile("mbarrier.arrive.shared.b64 _, [%0];" :: "r"(a) : "memory");
}
static __device__ __forceinline__ void mbar_cp_arrive(uint32_t a) {
    asm volatile("cp.async.mbarrier.arrive.shared.b64 [%0];" :: "r"(a) : "memory");
}
static __device__ __forceinline__ void mbar_wait(uint32_t a, uint32_t par) {
    asm volatile(
        "{\n .reg .pred P;\n"
        "WL%=: mbarrier.try_wait.parity.shared.b64 P, [%0], %1;\n"
        " @P bra WD%=;\n bra WL%=;\n WD%=:\n}"
        :: "r"(a), "r"(par) : "memory");
}
static __device__ __forceinline__ void cp16(uint32_t dst, const void* src) {
    asm volatile("cp.async.cg.shared.global [%0], [%1], 16;" :: "r"(dst), "l"(src) : "memory");
}
static __device__ __forceinline__ void ldsm4(uint32_t* r, uint32_t a) {
    asm volatile("ldmatrix.sync.aligned.m8n8.x4.shared.b16 {%0,%1,%2,%3}, [%4];"
                 : "=r"(r[0]), "=r"(r[1]), "=r"(r[2]), "=r"(r[3]) : "r"(a));
}
static __device__ __forceinline__ void ldsm4t(uint32_t* r, uint32_t a) {
    asm volatile("ldmatrix.sync.aligned.m8n8.x4.trans.shared.b16 {%0,%1,%2,%3}, [%4];"
                 : "=r"(r[0]), "=r"(r[1]), "=r"(r[2]), "=r"(r[3]) : "r"(a));
}
static __device__ __forceinline__ void mma16816(float* c, const uint32_t* a,
                                                uint32_t b0, uint32_t b1) {
    asm volatile(
        "mma.sync.aligned.m16n8k16.row.col.f32.f16.f16.f32 "
        "{%0,%1,%2,%3}, {%4,%5,%6,%7}, {%8,%9}, {%0,%1,%2,%3};"
        : "+f"(c[0]), "+f"(c[1]), "+f"(c[2]), "+f"(c[3])
        : "r"(a[0]), "r"(a[1]), "r"(a[2]), "r"(a[3]), "r"(b0), "r"(b1));
}
static __device__ __forceinline__ float leaky(float x) {
    return fmaxf(x, 0.f) + 0.2f * fminf(x, 0.f);
}

// ---------------- K1: h = x@W (fp32), s = h@a_w + a_b, h -> fp16 -----------
__global__ void __launch_bounds__(256) k_prep(const float* __restrict__ x,
                                              const float* __restrict__ W,
                                              const float* __restrict__ aw,
                                              const float* __restrict__ ab) {
    extern __shared__ float sm1[];
    float* xs = sm1;             // [64][132]
    float* ws = sm1 + 64 * 132;  // [128][128]
    const int tid = threadIdx.x;
    const int b = blockIdx.x >> 5;
    const int i0 = (blockIdx.x & 31) * 64;

    const float* xb = x + ((size_t)b * 2048 + i0) * 128;
#pragma unroll
    for (int k = 0; k < 32; k++) {
        int idx = tid + 256 * k;
        xs[(idx >> 7) * 132 + (idx & 127)] = xb[idx];
    }
#pragma unroll 8
    for (int k = 0; k < 64; k++) {
        int idx = tid + 256 * k;
        ws[idx] = W[idx];
    }
    __syncthreads();

    const int fg = tid & 15, rg = tid >> 4;
    const int f0 = fg * 8, r0 = rg * 4;
    float acc[4][8];
#pragma unroll
    for (int i = 0; i < 4; i++)
#pragma unroll
        for (int j = 0; j < 8; j++) acc[i][j] = 0.f;

#pragma unroll 4
    for (int k = 0; k < 128; k++) {
        float4 w0 = *(const float4*)&ws[k * 128 + f0];
        float4 w1 = *(const float4*)&ws[k * 128 + f0 + 4];
#pragma unroll
        for (int i = 0; i < 4; i++) {
            float a = xs[(r0 + i) * 132 + k];
            acc[i][0] += a * w0.x; acc[i][1] += a * w0.y;
            acc[i][2] += a * w0.z; acc[i][3] += a * w0.w;
            acc[i][4] += a * w1.x; acc[i][5] += a * w1.y;
            acc[i][6] += a * w1.z; acc[i][7] += a * w1.w;
        }
    }

    float awv[8];
#pragma unroll
    for (int j = 0; j < 8; j++) awv[j] = aw[f0 + j];
#pragma unroll
    for (int i = 0; i < 4; i++) {
        float s = 0.f;
#pragma unroll
        for (int j = 0; j < 8; j++) s += acc[i][j] * awv[j];
#pragma unroll
        for (int off = 8; off >= 1; off >>= 1) s += __shfl_xor_sync(0xffffffffu, s, off);
        if (fg == 0) g_s[b * 2048 + i0 + r0 + i] = s + ab[0];
    }

    // h -> fp16, natural layout [b][row][f], 16B stores
#pragma unroll
    for (int i = 0; i < 4; i++) {
        size_t base = ((size_t)b * 2048 + i0 + r0 + i) * 128 + f0;
        __half2 h2[4];
#pragma unroll
        for (int q = 0; q < 4; q++)
            h2[q] = __floats2half2_rn(acc[i][2 * q], acc[i][2 * q + 1]);
        *(uint4*)(g_h_hi + base) = *(uint4*)h2;
    }
}

// ---------------- K2: warp-specialized softmax + P@h via fp16 HMMA ---------
// 512 threads: warps 0-7 = MMA (2 per SMSP), warps 8-15 = producers.
// 4-stage pipeline. Per stage: P[64][72]h (144B pitch), H[64][136]h (272B)
static constexpr int NSTAGE  = 4;
static constexpr int P_PITCH = 144;
static constexpr int H_PITCH = 272;
static constexpr int OFF_HHI = 64 * P_PITCH;            // 9216
static constexpr int SBUF    = OFF_HHI + 64 * H_PITCH;  // 26624
static constexpr int OFF_SS   = NSTAGE * SBUF;          // 106496 (2048 f)
static constexpr int OFF_BIAS = OFF_SS + 8192;          // 114688 (128 f)
static constexpr int OFF_LS   = OFF_BIAS + 512;         // 115200 (64 f)
static constexpr int OFF_SMAX = OFF_LS + 256;           // 115456 (1 f)
static constexpr int OFF_MB   = OFF_SMAX + 16;          // 115472 (8 mbarriers)
static constexpr int SM2_SIZE = OFF_MB + 64;            // 115536

__global__ void __launch_bounds__(512) k_attn(const float* __restrict__ A,
                                              const float* __restrict__ bias,
                                              float* __restrict__ out) {
    extern __shared__ char sm[];
    const uint32_t sb = smem_u32(sm);
    const int tid = threadIdx.x, wid = tid >> 5, lane = tid & 31;
    const int b = blockIdx.x >> 5;
    const int i0 = (blockIdx.x & 31) << 6;

    float* ss = (float*)(sm + OFF_SS);
    {   // preload s for whole batch + bias
        const float4* sg = (const float4*)(g_s + b * 2048);
        float4* d = (float4*)ss;
        d[tid] = sg[tid];
        if (tid < 128) ((float*)(sm + OFF_BIAS))[tid] = bias[tid];
    }
    if (tid == 0) {
#pragma unroll
        for (int s = 0; s < NSTAGE; s++) {
            mbar_init(sb + OFF_MB + 8 * s, 256);                // full[s]
            mbar_init(sb + OFF_MB + 8 * (NSTAGE + s), 256);     // empty[s]
        }
    }
    __syncthreads();

    // batch-wide max of s (for fp16-safe exp shift)
    {
        float mx = -1e30f;
        for (int k = tid; k < 2048; k += 512) mx = fmaxf(mx, ss[k]);
#pragma unroll
        for (int off = 16; off >= 1; off >>= 1)
            mx = fmaxf(mx, __shfl_xor_sync(0xffffffffu, mx, off));
        if (lane == 0) ((float*)(sm + OFF_LS))[wid] = mx;  // scratch reuse
    }
    __syncthreads();
    if (tid == 0) {
        float mx = -1e30f;
#pragma unroll
        for (int w = 0; w < 16; w++) mx = fmaxf(mx, ((float*)(sm + OFF_LS))[w]);
        *(float*)(sm + OFF_SMAX) = mx;
    }
    __syncthreads();
    const float smax = *(const float*)(sm + OFF_SMAX);

    if (wid >= 8) {
        // ---------------- producer: P = exp(leaky(s_i+s_j)+A-m_i), H copies
        const int p = tid - 256;                         // 0..255
        const int rbase = p >> 4, cbase = (p & 15) * 4;  // 4 rows x 4 cols per thread
        const int fc = p & 15, jrb = p >> 4;
        const float* Abase = A + ((size_t)b * 2048 + i0) * 2048;
        const __half* Hhig = g_h_hi + (size_t)b * 2048 * 128;

        float s_i[4], m_i[4], lsum[4];
#pragma unroll
        for (int it = 0; it < 4; it++) {
            s_i[it] = ss[i0 + rbase + 16 * it];
            m_i[it] = leaky(s_i[it] + smax);
            lsum[it] = 0.f;
        }
        int phe[NSTAGE] = {1, 1, 1, 1};

#pragma unroll 1
        for (int t = 0; t < 32; t++) {
            const int j0 = t * 64, st = t & (NSTAGE - 1);
            const uint32_t bb = sb + st * SBUF;
            char* bp = sm + st * SBUF;

            // global A loads first (registers only; buffer may be busy)
            float4 av[4];
#pragma unroll
            for (int it = 0; it < 4; it++)
                av[it] = *(const float4*)(Abase + (size_t)(rbase + 16 * it) * 2048 + j0 + cbase);

            mbar_wait(sb + OFF_MB + 8 * (NSTAGE + st), phe[st]);
            phe[st] ^= 1;

            // h tile via cp.async: 64 rows x 16 col-chunks (16B)
#pragma unroll
            for (int c = 0; c < 4; c++) {
                const int jr = jrb + 16 * c;
                cp16(bb + OFF_HHI + jr * H_PITCH + fc * 16,
                     Hhig + (size_t)(j0 + jr) * 128 + fc * 8);
            }
            mbar_cp_arrive(sb + OFF_MB + 8 * st);  // async completion -> full[st]

            const float4 sv = *(const float4*)(ss + j0 + cbase);
#pragma unroll
            for (int it = 0; it < 4; it++) {
                const float si = s_i[it], m = m_i[it];
                float e0 = leaky(si + sv.x) - m;
                float e1 = leaky(si + sv.y) - m;
                float e2 = leaky(si + sv.z) - m;
                float e3 = leaky(si + sv.w) - m;
                float p0 = __expf(e0 + av[it].x), p1 = __expf(e1 + av[it].y);
                float p2 = __expf(e2 + av[it].z), p3 = __expf(e3 + av[it].w);
                lsum[it] += (p0 + p1) + (p2 + p3);
                __half2 hA = __floats2half2_rn(p0, p1);
                __half2 hB = __floats2half2_rn(p2, p3);
                *(uint2*)(bp + (rbase + 16 * it) * P_PITCH + cbase * 2) =
                    make_uint2(*(uint32_t*)&hA, *(uint32_t*)&hB);
            }
            mbar_arrive(sb + OFF_MB + 8 * st);
        }

        // per-row sums -> smem (16 lanes share a row)
        float* ls = (float*)(sm + OFF_LS);
#pragma unroll
        for (int it = 0; it < 4; it++) {
            float v = lsum[it];
            v += __shfl_xor_sync(0xffffffffu, v, 1);
            v += __shfl_xor_sync(0xffffffffu, v, 2);
            v += __shfl_xor_sync(0xffffffffu, v, 4);
            v += __shfl_xor_sync(0xffffffffu, v, 8);
            if ((p & 15) == 0) ls[rbase + 16 * it] = v;
        }
    } else {
        // ---------------- consumer: 16 rows x 64 cols per warp -------------
        const int r0 = (wid & 3) * 16;       // SMSP = wid&3; 2 warps/SMSP
        const int c0 = (wid >> 2) * 64;
        float acc[8][4];
#pragma unroll
        for (int nb = 0; nb < 8; nb++)
#pragma unroll
            for (int q = 0; q < 4; q++) acc[nb][q] = 0.f;

        const uint32_t arow = (uint32_t)((r0 + (lane & 15)) * P_PITCH + ((lane >> 4) << 4));
        const uint32_t brow = (uint32_t)((lane & 15) * H_PITCH + ((lane >> 4) << 4) + c0 * 2);
        int phf[NSTAGE] = {0, 0, 0, 0};

#pragma unroll 1
        for (int t = 0; t < 32; t++) {
            const int st = t & (NSTAGE - 1);
            const uint32_t bb = sb + st * SBUF;
            mbar_wait(sb + OFF_MB + 8 * st, phf[st]);
            phf[st] ^= 1;

#pragma unroll
            for (int kk = 0; kk < 4; kk++) {
                uint32_t ap[4];
                ldsm4(ap, bb + arow + kk * 32);
                const uint32_t hb = bb + OFF_HHI + brow + kk * 16 * H_PITCH;
                uint32_t bh[4][4];
#pragma unroll
                for (int n0 = 0; n0 < 4; n0++) ldsm4t(bh[n0], hb + n0 * 32);
#pragma unroll
                for (int n0 = 0; n0 < 4; n0++) {
                    mma16816(acc[2 * n0],     ap, bh[n0][0], bh[n0][1]);
                    mma16816(acc[2 * n0 + 1], ap, bh[n0][2], bh[n0][3]);
                }
            }
            mbar_arrive(sb + OFF_MB + 8 * (NSTAGE + st));
        }

        __syncthreads();  // producers publish ls

        const float* ls = (const float*)(sm + OFF_LS);
        const float* bs = (const float*)(sm + OFF_BIAS);
        const int row_lo = r0 + (lane >> 2);
        const float linv0 = 1.0f / ls[row_lo];
        const float linv1 = 1.0f / ls[row_lo + 8];
        float* orow0 = out + ((size_t)b * 2048 + i0 + row_lo) * 128;
        float* orow1 = orow0 + 8 * 128;
#pragma unroll
        for (int nb = 0; nb < 8; nb++) {
            const int col = c0 + nb * 8 + (lane & 3) * 2;
            float2 o0 = make_float2(acc[nb][0] * linv0 + bs[col],
                                    acc[nb][1] * linv0 + bs[col + 1]);
            float2 o1 = make_float2(acc[nb][2] * linv1 + bs[col],
                                    acc[nb][3] * linv1 + bs[col + 1]);
            *(float2*)(orow0 + col) = o0;
            *(float2*)(orow1 + col) = o1;
        }
        return;  // consumers done (producers hit the syncthreads below)
    }
    __syncthreads();  // producers: pair with consumers' syncthreads
}

extern "C" void kernel_launch(void* const* d_in, const int* in_sizes, int n_in,
                              void* d_out, int out_size) {
    (void)in_sizes; (void)n_in; (void)out_size;
    const float* x    = (const float*)d_in[0];
    const float* A    = (const float*)d_in[1];
    const float* W    = (const float*)d_in[2];
    const float* aw   = (const float*)d_in[3];
    const float* ab   = (const float*)d_in[4];
    const float* bias = (const float*)d_in[5];
    float* out = (float*)d_out;

    cudaFuncSetAttribute(k_prep, cudaFuncAttributeMaxDynamicSharedMemorySize, 99328);
    cudaFuncSetAttribute(k_attn, cudaFuncAttributeMaxDynamicSharedMemorySize, SM2_SIZE);

    k_prep<<<128, 256, 99328>>>(x, W, aw, ab);
    k_attn<<<128, 512, SM2_SIZE>>>(A, bias, out);
}

// round 9
// speedup vs baseline: 1.8839x; 1.2786x over previous
#include <cuda_runtime.h>
#include <cuda_fp16.h>
#include <cstdint>

// h (projected features) stored naturally [b][j][f] as fp16.
__device__ __align__(16) __half g_h_hi[4 * 2048 * 128];
__device__ float g_s[4 * 2048];

static __device__ __forceinline__ uint32_t smem_u32(const void* p) {
    uint32_t a;
    asm("{ .reg .u64 t; cvta.to.shared.u64 t, %1; cvt.u32.u64 %0, t; }" : "=r"(a) : "l"(p));
    return a;
}
static __device__ __forceinline__ void mbar_init(uint32_t a, uint32_t cnt) {
    asm volatile("mbarrier.init.shared.b64 [%0], %1;" :: "r"(a), "r"(cnt) : "memory");
}
static __device__ __forceinline__ void mbar_arrive(uint32_t a) {
    asm volatile("mbarrier.arrive.shared.b64 _, [%0];" :: "r"(a) : "memory");
}
static __device__ __forceinline__ void mbar_cp_arrive(uint32_t a) {
    asm volatile("cp.async.mbarrier.arrive.shared.b64 [%0];" :: "r"(a) : "memory");
}
static __device__ __forceinline__ void mbar_wait(uint32_t a, uint32_t par) {
    asm volatile(
        "{\n .reg .pred P;\n"
        "WL%=: mbarrier.try_wait.parity.shared.b64 P, [%0], %1;\n"
        " @P bra WD%=;\n bra WL%=;\n WD%=:\n}"
        :: "r"(a), "r"(par) : "memory");
}
static __device__ __forceinline__ void cp16(uint32_t dst, const void* src) {
    asm volatile("cp.async.cg.shared.global [%0], [%1], 16;" :: "r"(dst), "l"(src) : "memory");
}
static __device__ __forceinline__ void ldsm4(uint32_t* r, uint32_t a) {
    asm volatile("ldmatrix.sync.aligned.m8n8.x4.shared.b16 {%0,%1,%2,%3}, [%4];"
                 : "=r"(r[0]), "=r"(r[1]), "=r"(r[2]), "=r"(r[3]) : "r"(a));
}
static __device__ __forceinline__ void ldsm4t(uint32_t* r, uint32_t a) {
    asm volatile("ldmatrix.sync.aligned.m8n8.x4.trans.shared.b16 {%0,%1,%2,%3}, [%4];"
                 : "=r"(r[0]), "=r"(r[1]), "=r"(r[2]), "=r"(r[3]) : "r"(a));
}
static __device__ __forceinline__ void mma16816(float* c, const uint32_t* a,
                                                uint32_t b0, uint32_t b1) {
    asm volatile(
        "mma.sync.aligned.m16n8k16.row.col.f32.f16.f16.f32 "
        "{%0,%1,%2,%3}, {%4,%5,%6,%7}, {%8,%9}, {%0,%1,%2,%3};"
        : "+f"(c[0]), "+f"(c[1]), "+f"(c[2]), "+f"(c[3])
        : "r"(a[0]), "r"(a[1]), "r"(a[2]), "r"(a[3]), "r"(b0), "r"(b1));
}
static __device__ __forceinline__ float leaky(float x) {
    return fmaxf(x, 0.f) + 0.2f * fminf(x, 0.f);
}

// ---------------- K1: h = x@W via fp16 hi/lo 3-pass HMMA, s = h@a_w + ab ---
// block 256 (8 warps): warp w -> rows (w&3)*16..+16, cols (w>>2)*64..+64
static constexpr int XP       = 272;                 // pitch (128 halves + pad)
static constexpr int OFF_XHI  = 0;                   // 64 rows
static constexpr int OFF_XLO  = OFF_XHI + 64 * XP;   // 17408
static constexpr int OFF_WHI  = OFF_XLO + 64 * XP;   // 34816 (128 rows)
static constexpr int OFF_WLO  = OFF_WHI + 128 * XP;  // 69632
static constexpr int OFF_AW   = OFF_WLO + 128 * XP;  // 104448 (128 f)
static constexpr int OFF_SSM  = OFF_AW + 512;        // 104960 (64 f)
static constexpr int SM1_SIZE = OFF_SSM + 256;       // 105216

__global__ void __launch_bounds__(256) k_prep(const float* __restrict__ x,
                                              const float* __restrict__ W,
                                              const float* __restrict__ aw,
                                              const float* __restrict__ ab) {
    extern __shared__ char smp[];
    const uint32_t sbp = smem_u32(smp);
    const int tid = threadIdx.x, wid = tid >> 5, lane = tid & 31;
    const int b = blockIdx.x >> 5;
    const int i0 = (blockIdx.x & 31) * 64;

    // load + convert x (64x128 fp32) -> hi/lo fp16 smem
    const float4* xb = (const float4*)(x + ((size_t)b * 2048 + i0) * 128);
#pragma unroll
    for (int k = 0; k < 8; k++) {
        int idx = tid + 256 * k;          // 0..2047 float4s
        int row = idx >> 5, c4 = idx & 31;
        float4 v = xb[idx];
        __half2 h0 = __floats2half2_rn(v.x, v.y);
        __half2 h1 = __floats2half2_rn(v.z, v.w);
        float2 f0 = __half22float2(h0), f1 = __half22float2(h1);
        __half2 l0 = __floats2half2_rn(v.x - f0.x, v.y - f0.y);
        __half2 l1 = __floats2half2_rn(v.z - f1.x, v.w - f1.y);
        char* d = smp + OFF_XHI + row * XP + c4 * 8;
        *(uint2*)d = make_uint2(*(uint32_t*)&h0, *(uint32_t*)&h1);
        *(uint2*)(d + (OFF_XLO - OFF_XHI)) = make_uint2(*(uint32_t*)&l0, *(uint32_t*)&l1);
    }
    // load + convert W (128x128 fp32) -> hi/lo fp16 smem
    const float4* wb = (const float4*)W;
#pragma unroll
    for (int k = 0; k < 16; k++) {
        int idx = tid + 256 * k;          // 0..4095 float4s
        int row = idx >> 5, c4 = idx & 31;
        float4 v = wb[idx];
        __half2 h0 = __floats2half2_rn(v.x, v.y);
        __half2 h1 = __floats2half2_rn(v.z, v.w);
        float2 f0 = __half22float2(h0), f1 = __half22float2(h1);
        __half2 l0 = __floats2half2_rn(v.x - f0.x, v.y - f0.y);
        __half2 l1 = __floats2half2_rn(v.z - f1.x, v.w - f1.y);
        char* d = smp + OFF_WHI + row * XP + c4 * 8;
        *(uint2*)d = make_uint2(*(uint32_t*)&h0, *(uint32_t*)&h1);
        *(uint2*)(d + (OFF_WLO - OFF_WHI)) = make_uint2(*(uint32_t*)&l0, *(uint32_t*)&l1);
    }
    if (tid < 128) ((float*)(smp + OFF_AW))[tid] = aw[tid];
    if (tid < 64) ((float*)(smp + OFF_SSM))[tid] = 0.f;
    __syncthreads();

    // 3-pass HMMA: h = x_hi@W_hi + x_lo@W_hi + x_hi@W_lo (fp32 accum)
    const int r0 = (wid & 3) * 16, c0 = (wid >> 2) * 64;
    float acc[8][4];
#pragma unroll
    for (int nb = 0; nb < 8; nb++)
#pragma unroll
        for (int q = 0; q < 4; q++) acc[nb][q] = 0.f;

    const uint32_t arow = (uint32_t)((r0 + (lane & 15)) * XP + ((lane >> 4) << 4));
    const uint32_t brow = (uint32_t)((lane & 15) * XP + ((lane >> 4) << 4) + c0 * 2);
#pragma unroll
    for (int kk = 0; kk < 8; kk++) {
        uint32_t aph[4], apl[4];
        ldsm4(aph, sbp + OFF_XHI + arow + kk * 32);
        ldsm4(apl, sbp + OFF_XLO + arow + kk * 32);
        const uint32_t hb = sbp + OFF_WHI + brow + kk * 16 * XP;
#pragma unroll
        for (int n0 = 0; n0 < 4; n0++) {
            uint32_t bh[4], bl[4];
            ldsm4t(bh, hb + n0 * 32);
            ldsm4t(bl, hb + (OFF_WLO - OFF_WHI) + n0 * 32);
            mma16816(acc[2 * n0],     aph, bh[0], bh[1]);
            mma16816(acc[2 * n0 + 1], aph, bh[2], bh[3]);
            mma16816(acc[2 * n0],     apl, bh[0], bh[1]);
            mma16816(acc[2 * n0 + 1], apl, bh[2], bh[3]);
            mma16816(acc[2 * n0],     aph, bl[0], bl[1]);
            mma16816(acc[2 * n0 + 1], aph, bl[2], bl[3]);
        }
    }

    // epilogue: h -> fp16 global, s partial = h . aw
    const float* awp = (const float*)(smp + OFF_AW);
    float* ssm = (float*)(smp + OFF_SSM);
    const int row_lo = r0 + (lane >> 2);
    __half* hout0 = g_h_hi + ((size_t)b * 2048 + i0 + row_lo) * 128;
    __half* hout1 = hout0 + 8 * 128;
    float s0 = 0.f, s1 = 0.f;
#pragma unroll
    for (int nb = 0; nb < 8; nb++) {
        const int col = c0 + nb * 8 + (lane & 3) * 2;
        __half2 o0 = __floats2half2_rn(acc[nb][0], acc[nb][1]);
        __half2 o1 = __floats2half2_rn(acc[nb][2], acc[nb][3]);
        *(uint32_t*)(hout0 + col) = *(uint32_t*)&o0;
        *(uint32_t*)(hout1 + col) = *(uint32_t*)&o1;
        s0 += acc[nb][0] * awp[col] + acc[nb][1] * awp[col + 1];
        s1 += acc[nb][2] * awp[col] + acc[nb][3] * awp[col + 1];
    }
    s0 += __shfl_xor_sync(0xffffffffu, s0, 1);
    s0 += __shfl_xor_sync(0xffffffffu, s0, 2);
    s1 += __shfl_xor_sync(0xffffffffu, s1, 1);
    s1 += __shfl_xor_sync(0xffffffffu, s1, 2);
    if ((lane & 3) == 0) {
        atomicAdd(&ssm[row_lo], s0);
        atomicAdd(&ssm[row_lo + 8], s1);
    }
    __syncthreads();
    if (tid < 64) g_s[b * 2048 + i0 + tid] = ssm[tid] + ab[0];
}

// ---------------- K2: warp-specialized softmax + P@h via fp16 HMMA ---------
// 512 threads: warps 0-7 = MMA (2 per SMSP), warps 8-15 = producers.
// 4-stage pipeline. Per stage: P[64][72]h (144B pitch), H[64][136]h (272B)
static constexpr int NSTAGE  = 4;
static constexpr int P_PITCH = 144;
static constexpr int H_PITCH = 272;
static constexpr int OFF_HHI = 64 * P_PITCH;            // 9216
static constexpr int SBUF    = OFF_HHI + 64 * H_PITCH;  // 26624
static constexpr int OFF_SS   = NSTAGE * SBUF;          // 106496 (2048 f)
static constexpr int OFF_BIAS = OFF_SS + 8192;          // 114688 (128 f)
static constexpr int OFF_LS   = OFF_BIAS + 512;         // 115200 (64 f)
static constexpr int OFF_SMAX = OFF_LS + 256;           // 115456 (1 f)
static constexpr int OFF_MB   = OFF_SMAX + 16;          // 115472 (8 mbarriers)
static constexpr int SM2_SIZE = OFF_MB + 64;            // 115536

__global__ void __launch_bounds__(512) k_attn(const float* __restrict__ A,
                                              const float* __restrict__ bias,
                                              float* __restrict__ out) {
    extern __shared__ char sm[];
    const uint32_t sb = smem_u32(sm);
    const int tid = threadIdx.x, wid = tid >> 5, lane = tid & 31;
    const int b = blockIdx.x >> 5;
    const int i0 = (blockIdx.x & 31) << 6;

    float* ss = (float*)(sm + OFF_SS);
    {   // preload s for whole batch + bias
        const float4* sg = (const float4*)(g_s + b * 2048);
        float4* d = (float4*)ss;
        d[tid] = sg[tid];
        if (tid < 128) ((float*)(sm + OFF_BIAS))[tid] = bias[tid];
    }
    if (tid == 0) {
#pragma unroll
        for (int s = 0; s < NSTAGE; s++) {
            mbar_init(sb + OFF_MB + 8 * s, 256);                // full[s]
            mbar_init(sb + OFF_MB + 8 * (NSTAGE + s), 256);     // empty[s]
        }
    }
    __syncthreads();

    // batch-wide max of s (for fp16-safe exp shift)
    {
        float mx = -1e30f;
        for (int k = tid; k < 2048; k += 512) mx = fmaxf(mx, ss[k]);
#pragma unroll
        for (int off = 16; off >= 1; off >>= 1)
            mx = fmaxf(mx, __shfl_xor_sync(0xffffffffu, mx, off));
        if (lane == 0) ((float*)(sm + OFF_LS))[wid] = mx;  // scratch reuse
    }
    __syncthreads();
    if (tid == 0) {
        float mx = -1e30f;
#pragma unroll
        for (int w = 0; w < 16; w++) mx = fmaxf(mx, ((float*)(sm + OFF_LS))[w]);
        *(float*)(sm + OFF_SMAX) = mx;
    }
    __syncthreads();
    const float smax = *(const float*)(sm + OFF_SMAX);

    if (wid >= 8) {
        // ---------------- producer: P = exp(leaky(s_i+s_j)+A-m_i), H copies
        const int p = tid - 256;                         // 0..255
        const int rbase = p >> 4, cbase = (p & 15) * 4;  // 4 rows x 4 cols per thread
        const int fc = p & 15, jrb = p >> 4;
        const float* Abase = A + ((size_t)b * 2048 + i0) * 2048;
        const __half* Hhig = g_h_hi + (size_t)b * 2048 * 128;

        float s_i[4], m_i[4], lsum[4];
#pragma unroll
        for (int it = 0; it < 4; it++) {
            s_i[it] = ss[i0 + rbase + 16 * it];
            m_i[it] = leaky(s_i[it] + smax);
            lsum[it] = 0.f;
        }
        int phe[NSTAGE] = {1, 1, 1, 1};

        // prefetch A for chunk 0
        float4 av[4];
#pragma unroll
        for (int it = 0; it < 4; it++)
            av[it] = *(const float4*)(Abase + (size_t)(rbase + 16 * it) * 2048 + cbase);

#pragma unroll 1
        for (int t = 0; t < 32; t++) {
            const int j0 = t * 64, st = t & (NSTAGE - 1);
            const uint32_t bb = sb + st * SBUF;
            char* bp = sm + st * SBUF;

            // prefetch A for chunk t+1 (registers only; hides DRAM latency)
            const int j0n = (t < 31) ? (t + 1) * 64 : t * 64;
            float4 avn[4];
#pragma unroll
            for (int it = 0; it < 4; it++)
                avn[it] = *(const float4*)(Abase + (size_t)(rbase + 16 * it) * 2048 + j0n + cbase);

            mbar_wait(sb + OFF_MB + 8 * (NSTAGE + st), phe[st]);
            phe[st] ^= 1;

            // h tile via cp.async: 64 rows x 16 col-chunks (16B)
#pragma unroll
            for (int c = 0; c < 4; c++) {
                const int jr = jrb + 16 * c;
                cp16(bb + OFF_HHI + jr * H_PITCH + fc * 16,
                     Hhig + (size_t)(j0 + jr) * 128 + fc * 8);
            }
            mbar_cp_arrive(sb + OFF_MB + 8 * st);  // async completion -> full[st]

            const float4 sv = *(const float4*)(ss + j0 + cbase);
#pragma unroll
            for (int it = 0; it < 4; it++) {
                const float si = s_i[it], m = m_i[it];
                float e0 = leaky(si + sv.x) - m;
                float e1 = leaky(si + sv.y) - m;
                float e2 = leaky(si + sv.z) - m;
                float e3 = leaky(si + sv.w) - m;
                float p0 = __expf(e0 + av[it].x), p1 = __expf(e1 + av[it].y);
                float p2 = __expf(e2 + av[it].z), p3 = __expf(e3 + av[it].w);
                lsum[it] += (p0 + p1) + (p2 + p3);
                __half2 hA = __floats2half2_rn(p0, p1);
                __half2 hB = __floats2half2_rn(p2, p3);
                *(uint2*)(bp + (rbase + 16 * it) * P_PITCH + cbase * 2) =
                    make_uint2(*(uint32_t*)&hA, *(uint32_t*)&hB);
            }
            mbar_arrive(sb + OFF_MB + 8 * st);
#pragma unroll
            for (int it = 0; it < 4; it++) av[it] = avn[it];
        }

        // per-row sums -> smem (16 lanes share a row)
        float* ls = (float*)(sm + OFF_LS);
#pragma unroll
        for (int it = 0; it < 4; it++) {
            float v = lsum[it];
            v += __shfl_xor_sync(0xffffffffu, v, 1);
            v += __shfl_xor_sync(0xffffffffu, v, 2);
            v += __shfl_xor_sync(0xffffffffu, v, 4);
            v += __shfl_xor_sync(0xffffffffu, v, 8);
            if ((p & 15) == 0) ls[rbase + 16 * it] = v;
        }
    } else {
        // ---------------- consumer: 16 rows x 64 cols per warp -------------
        const int r0 = (wid & 3) * 16;       // SMSP = wid&3; 2 warps/SMSP
        const int c0 = (wid >> 2) * 64;
        float acc[8][4];
#pragma unroll
        for (int nb = 0; nb < 8; nb++)
#pragma unroll
            for (int q = 0; q < 4; q++) acc[nb][q] = 0.f;

        const uint32_t arow = (uint32_t)((r0 + (lane & 15)) * P_PITCH + ((lane >> 4) << 4));
        const uint32_t brow = (uint32_t)((lane & 15) * H_PITCH + ((lane >> 4) << 4) + c0 * 2);
        int phf[NSTAGE] = {0, 0, 0, 0};

#pragma unroll 1
        for (int t = 0; t < 32; t++) {
            const int st = t & (NSTAGE - 1);
            const uint32_t bb = sb + st * SBUF;
            mbar_wait(sb + OFF_MB + 8 * st, phf[st]);
            phf[st] ^= 1;

#pragma unroll
            for (int kk = 0; kk < 4; kk++) {
                uint32_t ap[4];
                ldsm4(ap, bb + arow + kk * 32);
                const uint32_t hb = bb + OFF_HHI + brow + kk * 16 * H_PITCH;
                uint32_t bh[4][4];
#pragma unroll
                for (int n0 = 0; n0 < 4; n0++) ldsm4t(bh[n0], hb + n0 * 32);
#pragma unroll
                for (int n0 = 0; n0 < 4; n0++) {
                    mma16816(acc[2 * n0],     ap, bh[n0][0], bh[n0][1]);
                    mma16816(acc[2 * n0 + 1], ap, bh[n0][2], bh[n0][3]);
                }
            }
            mbar_arrive(sb + OFF_MB + 8 * (NSTAGE + st));
        }

        __syncthreads();  // producers publish ls

        const float* ls = (const float*)(sm + OFF_LS);
        const float* bs = (const float*)(sm + OFF_BIAS);
        const int row_lo = r0 + (lane >> 2);
        const float linv0 = 1.0f / ls[row_lo];
        const float linv1 = 1.0f / ls[row_lo + 8];
        float* orow0 = out + ((size_t)b * 2048 + i0 + row_lo) * 128;
        float* orow1 = orow0 + 8 * 128;
#pragma unroll
        for (int nb = 0; nb < 8; nb++) {
            const int col = c0 + nb * 8 + (lane & 3) * 2;
            float2 o0 = make_float2(acc[nb][0] * linv0 + bs[col],
                                    acc[nb][1] * linv0 + bs[col + 1]);
            float2 o1 = make_float2(acc[nb][2] * linv1 + bs[col],
                                    acc[nb][3] * linv1 + bs[col + 1]);
            *(float2*)(orow0 + col) = o0;
            *(float2*)(orow1 + col) = o1;
        }
        return;  // consumers done (producers hit the syncthreads below)
    }
    __syncthreads();  // producers: pair with consumers' syncthreads
}

extern "C" void kernel_launch(void* const* d_in, const int* in_sizes, int n_in,
                              void* d_out, int out_size) {
    (void)in_sizes; (void)n_in; (void)out_size;
    const float* x    = (const float*)d_in[0];
    const float* A    = (const float*)d_in[1];
    const float* W    = (const float*)d_in[2];
    const float* aw   = (const float*)d_in[3];
    const float* ab   = (const float*)d_in[4];
    const float* bias = (const float*)d_in[5];
    float* out = (float*)d_out;

    cudaFuncSetAttribute(k_prep, cudaFuncAttributeMaxDynamicSharedMemorySize, SM1_SIZE);
    cudaFuncSetAttribute(k_attn, cudaFuncAttributeMaxDynamicSharedMemorySize, SM2_SIZE);

    k_prep<<<128, 256, SM1_SIZE>>>(x, W, aw, ab);
    k_attn<<<128, 512, SM2_SIZE>>>(A, bias, out);
}